// round 2
// baseline (speedup 1.0000x reference)
#include <cuda_runtime.h>
#include <cuda_bf16.h>

#define D_MODEL 1024
#define HEADS   16
#define DK      64
#define SEQ     2048
#define BATCH   4
#define BH      (BATCH*HEADS)

// Scratch (device globals: allocation-free)
__device__ float g_q[BATCH*HEADS*SEQ*DK];
__device__ float g_k[BATCH*HEADS*SEQ*DK];
__device__ float g_v[BATCH*HEADS*SEQ*DK];
__device__ float g_att[BATCH*SEQ*D_MODEL];

// ---------------------------------------------------------------------------
// GEMM (NT): C[m,n] = scale * sum_k A[m,k] * B[n,k]
// A: [M,1024] row-major, B: [1024,1024] row-major (W[d_out,d_in]).
// head_layout=1: write C to [b,h,s,d] (b=m>>11, s=m&2047, h=n>>6, d=n&63)
// head_layout=0: write C[m*1024+n]
// Tiles: BM=BN=128, BK=16. 256 threads, 8x8 micro-tile per thread.
// ---------------------------------------------------------------------------
__global__ __launch_bounds__(256)
void gemm_nt_kernel(const float* __restrict__ A, const float* __restrict__ B,
                    float* __restrict__ C, float scale, int head_layout)
{
    __shared__ float As[16][132];   // [k][m], +4 pad (stride mult of 4 for float4)
    __shared__ float Bs[16][132];   // [k][n]

    const int m0 = blockIdx.y * 128;
    const int n0 = blockIdx.x * 128;
    const int tid = threadIdx.x;
    const int tx = tid & 15;        // n group (8 cols each)
    const int ty = tid >> 4;        // m group (8 rows each)
    const int lr = tid >> 2;        // load row 0..63 (and +64)
    const int lc = (tid & 3) * 4;   // load col 0,4,8,12

    float acc[8][8];
#pragma unroll
    for (int i = 0; i < 8; i++)
#pragma unroll
        for (int j = 0; j < 8; j++) acc[i][j] = 0.f;

    const float* Arow0 = A + (size_t)(m0 + lr) * 1024 + lc;
    const float* Arow1 = Arow0 + (size_t)64 * 1024;
    const float* Brow0 = B + (size_t)(n0 + lr) * 1024 + lc;
    const float* Brow1 = Brow0 + (size_t)64 * 1024;

    for (int k0 = 0; k0 < 1024; k0 += 16) {
        float4 a0 = *(const float4*)(Arow0 + k0);
        float4 a1 = *(const float4*)(Arow1 + k0);
        float4 b0 = *(const float4*)(Brow0 + k0);
        float4 b1 = *(const float4*)(Brow1 + k0);
        As[lc + 0][lr] = a0.x; As[lc + 1][lr] = a0.y;
        As[lc + 2][lr] = a0.z; As[lc + 3][lr] = a0.w;
        As[lc + 0][lr + 64] = a1.x; As[lc + 1][lr + 64] = a1.y;
        As[lc + 2][lr + 64] = a1.z; As[lc + 3][lr + 64] = a1.w;
        Bs[lc + 0][lr] = b0.x; Bs[lc + 1][lr] = b0.y;
        Bs[lc + 2][lr] = b0.z; Bs[lc + 3][lr] = b0.w;
        Bs[lc + 0][lr + 64] = b1.x; Bs[lc + 1][lr + 64] = b1.y;
        Bs[lc + 2][lr + 64] = b1.z; Bs[lc + 3][lr + 64] = b1.w;
        __syncthreads();

#pragma unroll
        for (int k = 0; k < 16; k++) {
            float4 av0 = *(const float4*)&As[k][ty * 8];
            float4 av1 = *(const float4*)&As[k][ty * 8 + 4];
            float4 bv0 = *(const float4*)&Bs[k][tx * 8];
            float4 bv1 = *(const float4*)&Bs[k][tx * 8 + 4];
            float aa[8] = {av0.x, av0.y, av0.z, av0.w, av1.x, av1.y, av1.z, av1.w};
            float bb[8] = {bv0.x, bv0.y, bv0.z, bv0.w, bv1.x, bv1.y, bv1.z, bv1.w};
#pragma unroll
            for (int i = 0; i < 8; i++)
#pragma unroll
                for (int j = 0; j < 8; j++)
                    acc[i][j] += aa[i] * bb[j];
        }
        __syncthreads();
    }

    // epilogue
#pragma unroll
    for (int i = 0; i < 8; i++) {
        const int m = m0 + ty * 8 + i;
        float4 r0, r1;
        r0.x = acc[i][0] * scale; r0.y = acc[i][1] * scale;
        r0.z = acc[i][2] * scale; r0.w = acc[i][3] * scale;
        r1.x = acc[i][4] * scale; r1.y = acc[i][5] * scale;
        r1.z = acc[i][6] * scale; r1.w = acc[i][7] * scale;
        const int n = n0 + tx * 8;
        if (head_layout) {
            const int b = m >> 11, s = m & 2047;
            const int h = n >> 6, d = n & 63;   // tx*8 aligned: one head per thread
            float* p = g_q; // placeholder (overwritten below) -- avoids warning
            p = C + ((size_t)(b * HEADS + h) * SEQ + s) * DK + d;
            *(float4*)p = r0;
            *(float4*)(p + 4) = r1;
        } else {
            float* p = C + (size_t)m * 1024 + n;
            *(float4*)p = r0;
            *(float4*)(p + 4) = r1;
        }
    }
}

// ---------------------------------------------------------------------------
// Flash attention (causal), fp32. Q pre-scaled by 1/sqrt(dk).
// grid: (32 q-tiles, 64 bh). 256 threads.
// Q/K stored d-major in smem for conflict-free float4 reads; V k-major.
// Per-row streaming softmax state (m,l) in smem; 4-lane shfl reductions.
// ---------------------------------------------------------------------------
#define QS_OFF  0
#define KS_OFF  (64*68)
#define VS_OFF  (2*64*68)
#define SS_OFF  (3*64*68)
#define MS_OFF  (4*64*68)
#define LS_OFF  (4*64*68 + 64)
#define ALS_OFF (4*64*68 + 128)
#define ATTN_SMEM_FLOATS (4*64*68 + 192)

__global__ __launch_bounds__(256)
void attn_kernel(const float* __restrict__ Q, const float* __restrict__ K,
                 const float* __restrict__ V, float* __restrict__ Att)
{
    extern __shared__ float sm[];
    float* Qs = sm + QS_OFF;   // [d][q] stride 68
    float* Ks = sm + KS_OFF;   // [d][k] stride 68
    float* Vs = sm + VS_OFF;   // [k][d] stride 68
    float* Ss = sm + SS_OFF;   // [q][k] stride 68
    float* m_s  = sm + MS_OFF;
    float* l_s  = sm + LS_OFF;
    float* al_s = sm + ALS_OFF;

    const int qt = blockIdx.x;            // 0..31
    const int bh = blockIdx.y;            // 0..63
    const int tid = threadIdx.x;
    const int tx = tid & 15;              // k / d group
    const int ty = tid >> 4;              // q group
    const int lr = tid >> 2;              // load row 0..63
    const int lc = (tid & 3) * 16;        // load col base 0,16,32,48

    const size_t base = (size_t)bh * SEQ * DK;

    // Load Q tile (transposed to [d][q])
    {
        const float* qp = Q + base + (size_t)(qt * 64 + lr) * DK + lc;
#pragma unroll
        for (int w = 0; w < 4; w++) {
            float4 t = *(const float4*)(qp + w * 4);
            const int d = lc + w * 4;
            Qs[(d + 0) * 68 + lr] = t.x;
            Qs[(d + 1) * 68 + lr] = t.y;
            Qs[(d + 2) * 68 + lr] = t.z;
            Qs[(d + 3) * 68 + lr] = t.w;
        }
    }
    if (tid < 64) { m_s[tid] = -1e30f; l_s[tid] = 0.f; }

    float acc[4][4];
#pragma unroll
    for (int i = 0; i < 4; i++)
#pragma unroll
        for (int j = 0; j < 4; j++) acc[i][j] = 0.f;

    for (int kt = 0; kt <= qt; kt++) {
        __syncthreads();   // previous PV done reading Ss/Vs

        // Load K (transposed [d][k]) and V ([k][d])
        {
            const float* kp = K + base + (size_t)(kt * 64 + lr) * DK + lc;
            const float* vp = V + base + (size_t)(kt * 64 + lr) * DK + lc;
#pragma unroll
            for (int w = 0; w < 4; w++) {
                float4 t = *(const float4*)(kp + w * 4);
                const int d = lc + w * 4;
                Ks[(d + 0) * 68 + lr] = t.x;
                Ks[(d + 1) * 68 + lr] = t.y;
                Ks[(d + 2) * 68 + lr] = t.z;
                Ks[(d + 3) * 68 + lr] = t.w;
                float4 vv = *(const float4*)(vp + w * 4);
                *(float4*)&Vs[lr * 68 + d] = vv;
            }
        }
        __syncthreads();

        // S = Q K^T (4x4 per thread)
        float s[4][4];
#pragma unroll
        for (int i = 0; i < 4; i++)
#pragma unroll
            for (int j = 0; j < 4; j++) s[i][j] = 0.f;
#pragma unroll 8
        for (int d = 0; d < 64; d++) {
            float4 av = *(const float4*)&Qs[d * 68 + ty * 4];
            float4 bv = *(const float4*)&Ks[d * 68 + tx * 4];
            float aa[4] = {av.x, av.y, av.z, av.w};
            float bb[4] = {bv.x, bv.y, bv.z, bv.w};
#pragma unroll
            for (int i = 0; i < 4; i++)
#pragma unroll
                for (int j = 0; j < 4; j++)
                    s[i][j] += aa[i] * bb[j];
        }

        // causal mask on diagonal tile, then write to Ss
        const bool diag = (kt == qt);
#pragma unroll
        for (int i = 0; i < 4; i++) {
            const int q = ty * 4 + i;
#pragma unroll
            for (int j = 0; j < 4; j++) {
                const int k = tx * 4 + j;
                float v = s[i][j];
                if (diag && k > q) v = -1e30f;
                Ss[q * 68 + k] = v;
            }
        }
        __syncthreads();

        // streaming softmax: 4 lanes per row, 16 cols each
        {
            const int row = tid >> 2;
            const int seg = tid & 3;
            float* srow = Ss + row * 68 + seg * 16;
            float mx = -1e30f;
#pragma unroll
            for (int u = 0; u < 16; u++) mx = fmaxf(mx, srow[u]);
            mx = fmaxf(mx, __shfl_xor_sync(0xffffffffu, mx, 1));
            mx = fmaxf(mx, __shfl_xor_sync(0xffffffffu, mx, 2));
            const float m_old = m_s[row];
            const float m_new = fmaxf(m_old, mx);
            float sum = 0.f;
#pragma unroll
            for (int u = 0; u < 16; u++) {
                float e = __expf(srow[u] - m_new);
                srow[u] = e;
                sum += e;
            }
            sum += __shfl_xor_sync(0xffffffffu, sum, 1);
            sum += __shfl_xor_sync(0xffffffffu, sum, 2);
            __syncwarp();
            if (seg == 0) {
                const float alpha = __expf(m_old - m_new);
                m_s[row]  = m_new;
                l_s[row]  = l_s[row] * alpha + sum;
                al_s[row] = alpha;
            }
        }
        __syncthreads();

        // O = O*alpha + P @ V
#pragma unroll
        for (int i = 0; i < 4; i++) {
            const int q = ty * 4 + i;
            const float alpha = al_s[q];
#pragma unroll
            for (int j = 0; j < 4; j++) acc[i][j] *= alpha;
        }
#pragma unroll 4
        for (int k = 0; k < 64; k++) {
            float4 vv = *(const float4*)&Vs[k * 68 + tx * 4];
            float vb[4] = {vv.x, vv.y, vv.z, vv.w};
#pragma unroll
            for (int i = 0; i < 4; i++) {
                const float p = Ss[(ty * 4 + i) * 68 + k];
#pragma unroll
                for (int j = 0; j < 4; j++)
                    acc[i][j] += p * vb[j];
            }
        }
    }
    __syncthreads();

    // normalize & write to [b, s, h*64 + d]
    const int b = bh >> 4;
    const int h = bh & 15;
#pragma unroll
    for (int i = 0; i < 4; i++) {
        const int row = ty * 4 + i;
        const float inv = 1.f / l_s[row];
        float4 o;
        o.x = acc[i][0] * inv; o.y = acc[i][1] * inv;
        o.z = acc[i][2] * inv; o.w = acc[i][3] * inv;
        const int s = qt * 64 + row;
        float* p = Att + ((size_t)b * SEQ + s) * D_MODEL + h * DK + tx * 4;
        *(float4*)p = o;
    }
}

// ---------------------------------------------------------------------------
extern "C" void kernel_launch(void* const* d_in, const int* in_sizes, int n_in,
                              void* d_out, int out_size)
{
    (void)in_sizes; (void)n_in; (void)out_size;
    const float* x  = (const float*)d_in[0];
    const float* Wq = (const float*)d_in[1];
    const float* Wk = (const float*)d_in[2];
    const float* Wv = (const float*)d_in[3];
    const float* Wo = (const float*)d_in[4];
    float* out = (float*)d_out;

    float *qp, *kp, *vp, *ap;
    cudaGetSymbolAddress((void**)&qp, g_q);
    cudaGetSymbolAddress((void**)&kp, g_k);
    cudaGetSymbolAddress((void**)&vp, g_v);
    cudaGetSymbolAddress((void**)&ap, g_att);

    const int attn_smem = ATTN_SMEM_FLOATS * (int)sizeof(float);
    cudaFuncSetAttribute(attn_kernel,
                         cudaFuncAttributeMaxDynamicSharedMemorySize, attn_smem);

    dim3 gg(D_MODEL / 128, (BATCH * SEQ) / 128);   // (8, 64)
    const float qscale = 0.125f;                    // 1/sqrt(64)

    gemm_nt_kernel<<<gg, 256>>>(x, Wq, qp, qscale, 1);
    gemm_nt_kernel<<<gg, 256>>>(x, Wk, kp, 1.0f, 1);
    gemm_nt_kernel<<<gg, 256>>>(x, Wv, vp, 1.0f, 1);

    attn_kernel<<<dim3(SEQ / 64, BH), 256, attn_smem>>>(qp, kp, vp, ap);

    gemm_nt_kernel<<<gg, 256>>>(ap, Wo, out, 1.0f, 0);
}

// round 4
// speedup vs baseline: 1.4674x; 1.4674x over previous
#include <cuda_runtime.h>
#include <cuda_bf16.h>
#include <cstdint>

#define D_MODEL 1024
#define HEADS   16
#define DK      64
#define SEQ     2048
#define BATCH   4
#define BH      (BATCH*HEADS)
#define MTOT    (BATCH*SEQ)          // 8192

// ---------------- scratch (device globals: allocation-free) ----------------
__device__ float g_q[BATCH*HEADS*SEQ*DK];
__device__ float g_k[BATCH*HEADS*SEQ*DK];
__device__ float g_v[BATCH*HEADS*SEQ*DK];
__device__ float g_att[MTOT*D_MODEL];

__device__ __nv_bfloat16 g_xhi[MTOT*D_MODEL];
__device__ __nv_bfloat16 g_xlo[MTOT*D_MODEL];
__device__ __nv_bfloat16 g_whi[4][D_MODEL*D_MODEL];
__device__ __nv_bfloat16 g_wlo[4][D_MODEL*D_MODEL];
__device__ __nv_bfloat16 g_ahi[MTOT*D_MODEL];
__device__ __nv_bfloat16 g_alo[MTOT*D_MODEL];

// ---------------- helpers ----------------
__device__ __forceinline__ uint32_t smem_u32(const void* p) {
    uint32_t a;
    asm("{ .reg .u64 t; cvta.to.shared.u64 t, %1; cvt.u32.u64 %0, t; }"
        : "=r"(a) : "l"(p));
    return a;
}

__device__ __forceinline__ void cp16(uint32_t saddr, const void* gaddr) {
    asm volatile("cp.async.cg.shared.global [%0], [%1], 16;"
                 :: "r"(saddr), "l"(gaddr));
}
__device__ __forceinline__ void cp_commit() {
    asm volatile("cp.async.commit_group;");
}

__device__ __forceinline__ void ldmatrix4(uint32_t& r0, uint32_t& r1,
                                          uint32_t& r2, uint32_t& r3, uint32_t addr) {
    asm volatile("ldmatrix.sync.aligned.m8n8.x4.shared.b16 {%0,%1,%2,%3}, [%4];"
                 : "=r"(r0), "=r"(r1), "=r"(r2), "=r"(r3) : "r"(addr));
}

__device__ __forceinline__ void mma_bf16(float* c, const uint32_t* a, const uint32_t* b) {
    asm volatile("mma.sync.aligned.m16n8k16.row.col.f32.bf16.bf16.f32 "
                 "{%0,%1,%2,%3}, {%4,%5,%6,%7}, {%8,%9}, {%0,%1,%2,%3};"
                 : "+f"(c[0]), "+f"(c[1]), "+f"(c[2]), "+f"(c[3])
                 : "r"(a[0]), "r"(a[1]), "r"(a[2]), "r"(a[3]),
                   "r"(b[0]), "r"(b[1]));
}

// ---------------- split fp32 -> (hi, lo) bf16 ----------------
__global__ void split_kernel(const float* __restrict__ in,
                             __nv_bfloat16* __restrict__ hi,
                             __nv_bfloat16* __restrict__ lo, int n4)
{
    int i = blockIdx.x * blockDim.x + threadIdx.x;
    if (i >= n4) return;
    float4 v = ((const float4*)in)[i];
    __nv_bfloat16 h0 = __float2bfloat16(v.x);
    __nv_bfloat16 h1 = __float2bfloat16(v.y);
    __nv_bfloat16 h2 = __float2bfloat16(v.z);
    __nv_bfloat16 h3 = __float2bfloat16(v.w);
    __nv_bfloat16 l0 = __float2bfloat16(v.x - __bfloat162float(h0));
    __nv_bfloat16 l1 = __float2bfloat16(v.y - __bfloat162float(h1));
    __nv_bfloat16 l2 = __float2bfloat16(v.z - __bfloat162float(h2));
    __nv_bfloat16 l3 = __float2bfloat16(v.w - __bfloat162float(h3));
    hi[4*i+0] = h0; hi[4*i+1] = h1; hi[4*i+2] = h2; hi[4*i+3] = h3;
    lo[4*i+0] = l0; lo[4*i+1] = l1; lo[4*i+2] = l2; lo[4*i+3] = l3;
}

// ---------------- mma.sync split-bf16 GEMM ----------------
// C[m,n] = scale * sum_k A[m,k]*B[n,k]  (NT; both K-contiguous)
// CTA tile 128x64, K-chunk 32, 2-stage cp.async pipeline, 8 warps (4m x 2n),
// warp tile 32x32 (2 m16-frags x 4 n8-frags), 3-term split-bf16.
#define BM 128
#define BN 64
#define BK 32
#define SSTRIDE 40                    // b16 stride per row (80 B, pad 8)
#define A_TILE_B (BM * SSTRIDE * 2)   // 10240
#define B_TILE_B (BN * SSTRIDE * 2)   // 5120
#define STAGE_B  (2*A_TILE_B + 2*B_TILE_B)   // 30720
#define AHI_OFF  0
#define ALO_OFF  (A_TILE_B)
#define BHI_OFF  (2*A_TILE_B)
#define BLO_OFF  (2*A_TILE_B + B_TILE_B)
#define GEMM_SMEM (2*STAGE_B)         // 61440

__global__ __launch_bounds__(256)
void gemm_mma_kernel(const __nv_bfloat16* __restrict__ Ahi,
                     const __nv_bfloat16* __restrict__ Alo,
                     const __nv_bfloat16* __restrict__ Bhi,
                     const __nv_bfloat16* __restrict__ Blo,
                     float* __restrict__ C, float scale, int head_layout)
{
    extern __shared__ char smem[];
    const uint32_t sbase = smem_u32(smem);
    const int tid = threadIdx.x;
    const int wid = tid >> 5;
    const int lane = tid & 31;
    const int wm = wid & 3;           // m warp 0..3
    const int wn = wid >> 2;          // n warp 0..1

    const int m0 = blockIdx.y * BM;
    const int n0 = blockIdx.x * BN;

    const __nv_bfloat16* Ah = Ahi + (size_t)m0 * 1024;
    const __nv_bfloat16* Al = Alo + (size_t)m0 * 1024;
    const __nv_bfloat16* Bh = Bhi + (size_t)n0 * 1024;
    const __nv_bfloat16* Bl = Blo + (size_t)n0 * 1024;

    // loader indices: each 16B = 8 b16; A rows need 4 transfers, B same.
    const int lrow = tid >> 2;            // 0..63
    const int lc16 = tid & 3;             // 0..3 (k offset lc16*8)

    auto load_stage = [&](int ch, int st) {
        const int k0 = ch * BK;
        const uint32_t sb = sbase + st * STAGE_B;
        const uint32_t soff = (uint32_t)(lrow * (SSTRIDE*2) + lc16 * 16);
        const size_t goff = (size_t)lrow * 1024 + k0 + lc16 * 8;
        // A tiles: rows lrow and lrow+64
        cp16(sb + AHI_OFF + soff, Ah + goff);
        cp16(sb + AHI_OFF + soff + 64*(SSTRIDE*2), Ah + goff + (size_t)64*1024);
        cp16(sb + ALO_OFF + soff, Al + goff);
        cp16(sb + ALO_OFF + soff + 64*(SSTRIDE*2), Al + goff + (size_t)64*1024);
        // B tiles: rows 0..63
        cp16(sb + BHI_OFF + soff, Bh + goff);
        cp16(sb + BLO_OFF + soff, Bl + goff);
    };

    float acc[2][4][4];
#pragma unroll
    for (int i = 0; i < 2; i++)
#pragma unroll
        for (int j = 0; j < 4; j++)
#pragma unroll
            for (int t = 0; t < 4; t++) acc[i][j][t] = 0.f;

    load_stage(0, 0);
    cp_commit();

    const int NCH = 1024 / BK;   // 32
    for (int ch = 0; ch < NCH; ch++) {
        if (ch + 1 < NCH) { load_stage(ch + 1, (ch + 1) & 1); cp_commit(); }
        if (ch + 1 < NCH) asm volatile("cp.async.wait_group 1;");
        else              asm volatile("cp.async.wait_group 0;");
        __syncthreads();

        const uint32_t sb = sbase + (ch & 1) * STAGE_B;
#pragma unroll
        for (int ks = 0; ks < 2; ks++) {
            const int k16 = ks * 16;
            // ---- A fragments (hi & lo): 2 m16 frags ----
            uint32_t ahi[2][4], alo[2][4];
#pragma unroll
            for (int mf = 0; mf < 2; mf++) {
                const int row = wm * 32 + mf * 16 + (lane & 15);
                const int kc  = k16 + ((lane >> 4) << 3);
                const uint32_t off = (uint32_t)(row * (SSTRIDE*2) + kc * 2);
                ldmatrix4(ahi[mf][0], ahi[mf][1], ahi[mf][2], ahi[mf][3],
                          sb + AHI_OFF + off);
                ldmatrix4(alo[mf][0], alo[mf][1], alo[mf][2], alo[mf][3],
                          sb + ALO_OFF + off);
            }
            // ---- B fragments (hi & lo): 4 n8 frags as 2 x ldmatrix.x4 ----
            uint32_t bhi[4][2], blo[4][2];
#pragma unroll
            for (int nf16 = 0; nf16 < 2; nf16++) {
                const int nrow = wn * 32 + nf16 * 16 + ((lane >> 4) << 3) + (lane & 7);
                const int kc   = k16 + (((lane >> 3) & 1) << 3);
                const uint32_t off = (uint32_t)(nrow * (SSTRIDE*2) + kc * 2);
                ldmatrix4(bhi[nf16*2][0], bhi[nf16*2][1],
                          bhi[nf16*2+1][0], bhi[nf16*2+1][1], sb + BHI_OFF + off);
                ldmatrix4(blo[nf16*2][0], blo[nf16*2][1],
                          blo[nf16*2+1][0], blo[nf16*2+1][1], sb + BLO_OFF + off);
            }
            // ---- 3-term MMA ----
#pragma unroll
            for (int mf = 0; mf < 2; mf++)
#pragma unroll
                for (int nf = 0; nf < 4; nf++) {
                    mma_bf16(acc[mf][nf], ahi[mf], bhi[nf]);
                    mma_bf16(acc[mf][nf], ahi[mf], blo[nf]);
                    mma_bf16(acc[mf][nf], alo[mf], bhi[nf]);
                }
        }
        __syncthreads();
    }

    // ---- epilogue: direct fp32 stores ----
#pragma unroll
    for (int mf = 0; mf < 2; mf++) {
#pragma unroll
        for (int nf = 0; nf < 4; nf++) {
            const int m_base = m0 + wm * 32 + mf * 16;
            const int n = n0 + wn * 32 + nf * 8 + (lane & 3) * 2;
            const int r0 = m_base + (lane >> 2);
            const int r1 = r0 + 8;
            float2 v0 = make_float2(acc[mf][nf][0] * scale, acc[mf][nf][1] * scale);
            float2 v1 = make_float2(acc[mf][nf][2] * scale, acc[mf][nf][3] * scale);
            if (head_layout) {
                const int h = n >> 6, d = n & 63;
                const int b0 = r0 >> 11, s0 = r0 & 2047;
                const int b1 = r1 >> 11, s1 = r1 & 2047;
                *(float2*)(C + ((size_t)(b0 * HEADS + h) * SEQ + s0) * DK + d) = v0;
                *(float2*)(C + ((size_t)(b1 * HEADS + h) * SEQ + s1) * DK + d) = v1;
            } else {
                *(float2*)(C + (size_t)r0 * 1024 + n) = v0;
                *(float2*)(C + (size_t)r1 * 1024 + n) = v1;
            }
        }
    }
}

// ---------------------------------------------------------------------------
// Flash attention (causal), fp32. Q pre-scaled by 1/sqrt(dk). (unchanged)
// ---------------------------------------------------------------------------
#define QS_OFF  0
#define KS_OFF  (64*68)
#define VS_OFF  (2*64*68)
#define SS_OFF  (3*64*68)
#define MS_OFF  (4*64*68)
#define LS_OFF  (4*64*68 + 64)
#define ALS_OFF (4*64*68 + 128)
#define ATTN_SMEM_FLOATS (4*64*68 + 192)

__global__ __launch_bounds__(256)
void attn_kernel(const float* __restrict__ Q, const float* __restrict__ K,
                 const float* __restrict__ V, float* __restrict__ Att)
{
    extern __shared__ float sm[];
    float* Qs = sm + QS_OFF;
    float* Ks = sm + KS_OFF;
    float* Vs = sm + VS_OFF;
    float* Ss = sm + SS_OFF;
    float* m_s  = sm + MS_OFF;
    float* l_s  = sm + LS_OFF;
    float* al_s = sm + ALS_OFF;

    const int qt = blockIdx.x;
    const int bh = blockIdx.y;
    const int tid = threadIdx.x;
    const int tx = tid & 15;
    const int ty = tid >> 4;
    const int lr = tid >> 2;
    const int lc = (tid & 3) * 16;

    const size_t base = (size_t)bh * SEQ * DK;

    {
        const float* qp = Q + base + (size_t)(qt * 64 + lr) * DK + lc;
#pragma unroll
        for (int w = 0; w < 4; w++) {
            float4 t = *(const float4*)(qp + w * 4);
            const int d = lc + w * 4;
            Qs[(d + 0) * 68 + lr] = t.x;
            Qs[(d + 1) * 68 + lr] = t.y;
            Qs[(d + 2) * 68 + lr] = t.z;
            Qs[(d + 3) * 68 + lr] = t.w;
        }
    }
    if (tid < 64) { m_s[tid] = -1e30f; l_s[tid] = 0.f; }

    float acc[4][4];
#pragma unroll
    for (int i = 0; i < 4; i++)
#pragma unroll
        for (int j = 0; j < 4; j++) acc[i][j] = 0.f;

    for (int kt = 0; kt <= qt; kt++) {
        __syncthreads();
        {
            const float* kp = K + base + (size_t)(kt * 64 + lr) * DK + lc;
            const float* vp = V + base + (size_t)(kt * 64 + lr) * DK + lc;
#pragma unroll
            for (int w = 0; w < 4; w++) {
                float4 t = *(const float4*)(kp + w * 4);
                const int d = lc + w * 4;
                Ks[(d + 0) * 68 + lr] = t.x;
                Ks[(d + 1) * 68 + lr] = t.y;
                Ks[(d + 2) * 68 + lr] = t.z;
                Ks[(d + 3) * 68 + lr] = t.w;
                float4 vv = *(const float4*)(vp + w * 4);
                *(float4*)&Vs[lr * 68 + d] = vv;
            }
        }
        __syncthreads();

        float s[4][4];
#pragma unroll
        for (int i = 0; i < 4; i++)
#pragma unroll
            for (int j = 0; j < 4; j++) s[i][j] = 0.f;
#pragma unroll 8
        for (int d = 0; d < 64; d++) {
            float4 av = *(const float4*)&Qs[d * 68 + ty * 4];
            float4 bv = *(const float4*)&Ks[d * 68 + tx * 4];
            float aa[4] = {av.x, av.y, av.z, av.w};
            float bb[4] = {bv.x, bv.y, bv.z, bv.w};
#pragma unroll
            for (int i = 0; i < 4; i++)
#pragma unroll
                for (int j = 0; j < 4; j++)
                    s[i][j] += aa[i] * bb[j];
        }

        const bool diag = (kt == qt);
#pragma unroll
        for (int i = 0; i < 4; i++) {
            const int q = ty * 4 + i;
#pragma unroll
            for (int j = 0; j < 4; j++) {
                const int k = tx * 4 + j;
                float v = s[i][j];
                if (diag && k > q) v = -1e30f;
                Ss[q * 68 + k] = v;
            }
        }
        __syncthreads();

        {
            const int row = tid >> 2;
            const int seg = tid & 3;
            float* srow = Ss + row * 68 + seg * 16;
            float mx = -1e30f;
#pragma unroll
            for (int u = 0; u < 16; u++) mx = fmaxf(mx, srow[u]);
            mx = fmaxf(mx, __shfl_xor_sync(0xffffffffu, mx, 1));
            mx = fmaxf(mx, __shfl_xor_sync(0xffffffffu, mx, 2));
            const float m_old = m_s[row];
            const float m_new = fmaxf(m_old, mx);
            float sum = 0.f;
#pragma unroll
            for (int u = 0; u < 16; u++) {
                float e = __expf(srow[u] - m_new);
                srow[u] = e;
                sum += e;
            }
            sum += __shfl_xor_sync(0xffffffffu, sum, 1);
            sum += __shfl_xor_sync(0xffffffffu, sum, 2);
            __syncwarp();
            if (seg == 0) {
                const float alpha = __expf(m_old - m_new);
                m_s[row]  = m_new;
                l_s[row]  = l_s[row] * alpha + sum;
                al_s[row] = alpha;
            }
        }
        __syncthreads();

#pragma unroll
        for (int i = 0; i < 4; i++) {
            const int q = ty * 4 + i;
            const float alpha = al_s[q];
#pragma unroll
            for (int j = 0; j < 4; j++) acc[i][j] *= alpha;
        }
#pragma unroll 4
        for (int k = 0; k < 64; k++) {
            float4 vv = *(const float4*)&Vs[k * 68 + tx * 4];
            float vb[4] = {vv.x, vv.y, vv.z, vv.w};
#pragma unroll
            for (int i = 0; i < 4; i++) {
                const float p = Ss[(ty * 4 + i) * 68 + k];
#pragma unroll
                for (int j = 0; j < 4; j++)
                    acc[i][j] += p * vb[j];
            }
        }
    }
    __syncthreads();

    const int b = bh >> 4;
    const int h = bh & 15;
#pragma unroll
    for (int i = 0; i < 4; i++) {
        const int row = ty * 4 + i;
        const float inv = 1.f / l_s[row];
        float4 o;
        o.x = acc[i][0] * inv; o.y = acc[i][1] * inv;
        o.z = acc[i][2] * inv; o.w = acc[i][3] * inv;
        const int s = qt * 64 + row;
        float* p = Att + ((size_t)b * SEQ + s) * D_MODEL + h * DK + tx * 4;
        *(float4*)p = o;
    }
}

// ---------------------------------------------------------------------------
extern "C" void kernel_launch(void* const* d_in, const int* in_sizes, int n_in,
                              void* d_out, int out_size)
{
    (void)in_sizes; (void)n_in; (void)out_size;
    const float* x  = (const float*)d_in[0];
    const float* Wq = (const float*)d_in[1];
    const float* Wk = (const float*)d_in[2];
    const float* Wv = (const float*)d_in[3];
    const float* Wo = (const float*)d_in[4];
    float* out = (float*)d_out;

    float *qp, *kp, *vp, *ap;
    cudaGetSymbolAddress((void**)&qp, g_q);
    cudaGetSymbolAddress((void**)&kp, g_k);
    cudaGetSymbolAddress((void**)&vp, g_v);
    cudaGetSymbolAddress((void**)&ap, g_att);
    __nv_bfloat16 *xhi, *xlo, *whi, *wlo, *ahi, *alo;
    cudaGetSymbolAddress((void**)&xhi, g_xhi);
    cudaGetSymbolAddress((void**)&xlo, g_xlo);
    cudaGetSymbolAddress((void**)&whi, g_whi);
    cudaGetSymbolAddress((void**)&wlo, g_wlo);
    cudaGetSymbolAddress((void**)&ahi, g_ahi);
    cudaGetSymbolAddress((void**)&alo, g_alo);

    const int attn_smem = ATTN_SMEM_FLOATS * (int)sizeof(float);
    cudaFuncSetAttribute(attn_kernel,
                         cudaFuncAttributeMaxDynamicSharedMemorySize, attn_smem);
    cudaFuncSetAttribute(gemm_mma_kernel,
                         cudaFuncAttributeMaxDynamicSharedMemorySize, GEMM_SMEM);

    const int WN4 = D_MODEL * D_MODEL / 4;   // 262144
    const int XN4 = MTOT * D_MODEL / 4;      // 2097152
    const float* Ws[4] = {Wq, Wk, Wv, Wo};

    split_kernel<<<XN4 / 256, 256>>>(x, xhi, xlo, XN4);
    for (int i = 0; i < 4; i++)
        split_kernel<<<WN4 / 256, 256>>>(Ws[i], whi + (size_t)i * D_MODEL * D_MODEL,
                                         wlo + (size_t)i * D_MODEL * D_MODEL, WN4);

    dim3 gg(D_MODEL / BN, MTOT / BM);        // (16, 64)
    const float qscale = 0.125f;             // 1/sqrt(64)
    const size_t WSZ = (size_t)D_MODEL * D_MODEL;

    gemm_mma_kernel<<<gg, 256, GEMM_SMEM>>>(xhi, xlo, whi + 0*WSZ, wlo + 0*WSZ, qp, qscale, 1);
    gemm_mma_kernel<<<gg, 256, GEMM_SMEM>>>(xhi, xlo, whi + 1*WSZ, wlo + 1*WSZ, kp, 1.0f, 1);
    gemm_mma_kernel<<<gg, 256, GEMM_SMEM>>>(xhi, xlo, whi + 2*WSZ, wlo + 2*WSZ, vp, 1.0f, 1);

    attn_kernel<<<dim3(SEQ / 64, BH), 256, attn_smem>>>(qp, kp, vp, ap);

    split_kernel<<<XN4 / 256, 256>>>(ap, ahi, alo, XN4);
    gemm_mma_kernel<<<gg, 256, GEMM_SMEM>>>(ahi, alo, whi + 3*WSZ, wlo + 3*WSZ, out, 1.0f, 0);
}

// round 5
// speedup vs baseline: 2.6403x; 1.7993x over previous
#include <cuda_runtime.h>
#include <cuda_bf16.h>
#include <cstdint>

#define D_MODEL 1024
#define HEADS   16
#define DK      64
#define SEQ     2048
#define BATCH   4
#define BH      (BATCH*HEADS)
#define MTOT    (BATCH*SEQ)          // 8192

// ---------------- scratch (device globals: allocation-free) ----------------
__device__ __nv_bfloat16 g_xhi[MTOT*D_MODEL];
__device__ __nv_bfloat16 g_xlo[MTOT*D_MODEL];
__device__ __nv_bfloat16 g_whi[4][D_MODEL*D_MODEL];
__device__ __nv_bfloat16 g_wlo[4][D_MODEL*D_MODEL];
__device__ __nv_bfloat16 g_qhi[BH*SEQ*DK];
__device__ __nv_bfloat16 g_qlo[BH*SEQ*DK];
__device__ __nv_bfloat16 g_khi[BH*SEQ*DK];
__device__ __nv_bfloat16 g_klo[BH*SEQ*DK];
__device__ __nv_bfloat16 g_vhi[BH*DK*SEQ];   // transposed [bh][d][s]
__device__ __nv_bfloat16 g_vlo[BH*DK*SEQ];
__device__ __nv_bfloat16 g_ahi[MTOT*D_MODEL];
__device__ __nv_bfloat16 g_alo[MTOT*D_MODEL];

// ---------------- helpers ----------------
__device__ __forceinline__ uint32_t smem_u32(const void* p) {
    uint32_t a;
    asm("{ .reg .u64 t; cvta.to.shared.u64 t, %1; cvt.u32.u64 %0, t; }"
        : "=r"(a) : "l"(p));
    return a;
}
__device__ __forceinline__ void cp16(uint32_t saddr, const void* gaddr) {
    asm volatile("cp.async.cg.shared.global [%0], [%1], 16;"
                 :: "r"(saddr), "l"(gaddr));
}
__device__ __forceinline__ void cp_commit() {
    asm volatile("cp.async.commit_group;");
}
__device__ __forceinline__ void ldmatrix4(uint32_t& r0, uint32_t& r1,
                                          uint32_t& r2, uint32_t& r3, uint32_t addr) {
    asm volatile("ldmatrix.sync.aligned.m8n8.x4.shared.b16 {%0,%1,%2,%3}, [%4];"
                 : "=r"(r0), "=r"(r1), "=r"(r2), "=r"(r3) : "r"(addr));
}
__device__ __forceinline__ void mma_bf16(float* c, const uint32_t* a, const uint32_t* b) {
    asm volatile("mma.sync.aligned.m16n8k16.row.col.f32.bf16.bf16.f32 "
                 "{%0,%1,%2,%3}, {%4,%5,%6,%7}, {%8,%9}, {%0,%1,%2,%3};"
                 : "+f"(c[0]), "+f"(c[1]), "+f"(c[2]), "+f"(c[3])
                 : "r"(a[0]), "r"(a[1]), "r"(a[2]), "r"(a[3]),
                   "r"(b[0]), "r"(b[1]));
}
__device__ __forceinline__ uint32_t pack_hi(float a, float b, float& ra, float& rb) {
    __nv_bfloat16 h0 = __float2bfloat16(a);
    __nv_bfloat16 h1 = __float2bfloat16(b);
    ra = a - __bfloat162float(h0);
    rb = b - __bfloat162float(h1);
    __nv_bfloat162 t = __halves2bfloat162(h0, h1);
    return *(uint32_t*)&t;
}
__device__ __forceinline__ uint32_t pack_bf(float a, float b) {
    __nv_bfloat162 t = __halves2bfloat162(__float2bfloat16(a), __float2bfloat16(b));
    return *(uint32_t*)&t;
}
__device__ __forceinline__ void store_hl(__nv_bfloat16* hi, __nv_bfloat16* lo,
                                         size_t idx, float v0, float v1) {
    __nv_bfloat16 h0 = __float2bfloat16(v0);
    __nv_bfloat16 h1 = __float2bfloat16(v1);
    *(__nv_bfloat162*)(hi + idx) = __halves2bfloat162(h0, h1);
    *(__nv_bfloat162*)(lo + idx) = __halves2bfloat162(
        __float2bfloat16(v0 - __bfloat162float(h0)),
        __float2bfloat16(v1 - __bfloat162float(h1)));
}

// ---------------- split fp32 -> (hi, lo) bf16 ----------------
__global__ void split_kernel(const float* __restrict__ in,
                             __nv_bfloat16* __restrict__ hi,
                             __nv_bfloat16* __restrict__ lo, int n4)
{
    int i = blockIdx.x * blockDim.x + threadIdx.x;
    if (i >= n4) return;
    float4 v = ((const float4*)in)[i];
    float r0, r1, r2, r3;
    uint32_t h01 = pack_hi(v.x, v.y, r0, r1);
    uint32_t h23 = pack_hi(v.z, v.w, r2, r3);
    ((uint32_t*)hi)[2*i+0] = h01;
    ((uint32_t*)hi)[2*i+1] = h23;
    ((uint32_t*)lo)[2*i+0] = pack_bf(r0, r1);
    ((uint32_t*)lo)[2*i+1] = pack_bf(r2, r3);
}

// ---------------- mma.sync split-bf16 GEMM ----------------
// C[m,n] = scale * sum_k A[m,k]*B[n,k]  (NT)
// mode 0: fp32 row-major to Cf
// mode 1: bf16 hi/lo to [bh][s][d]   (Q, K)
// mode 2: bf16 hi/lo to [bh][d][s]   (V transposed)
#define BM 128
#define BN 64
#define BK 32
#define SSTRIDE 40
#define A_TILE_B (BM * SSTRIDE * 2)
#define B_TILE_B (BN * SSTRIDE * 2)
#define STAGE_B  (2*A_TILE_B + 2*B_TILE_B)
#define AHI_OFF  0
#define ALO_OFF  (A_TILE_B)
#define BHI_OFF  (2*A_TILE_B)
#define BLO_OFF  (2*A_TILE_B + B_TILE_B)
#define GEMM_SMEM (2*STAGE_B)

__global__ __launch_bounds__(256)
void gemm_mma_kernel(const __nv_bfloat16* __restrict__ Ahi,
                     const __nv_bfloat16* __restrict__ Alo,
                     const __nv_bfloat16* __restrict__ Bhi,
                     const __nv_bfloat16* __restrict__ Blo,
                     float* __restrict__ Cf,
                     __nv_bfloat16* __restrict__ Chi,
                     __nv_bfloat16* __restrict__ Clo,
                     float scale, int mode)
{
    extern __shared__ char smem[];
    const uint32_t sbase = smem_u32(smem);
    const int tid = threadIdx.x;
    const int wid = tid >> 5;
    const int lane = tid & 31;
    const int wm = wid & 3;
    const int wn = wid >> 2;

    const int m0 = blockIdx.y * BM;
    const int n0 = blockIdx.x * BN;

    const __nv_bfloat16* Ah = Ahi + (size_t)m0 * 1024;
    const __nv_bfloat16* Al = Alo + (size_t)m0 * 1024;
    const __nv_bfloat16* Bh = Bhi + (size_t)n0 * 1024;
    const __nv_bfloat16* Bl = Blo + (size_t)n0 * 1024;

    const int lrow = tid >> 2;
    const int lc16 = tid & 3;

    auto load_stage = [&](int ch, int st) {
        const int k0 = ch * BK;
        const uint32_t sb = sbase + st * STAGE_B;
        const uint32_t soff = (uint32_t)(lrow * (SSTRIDE*2) + lc16 * 16);
        const size_t goff = (size_t)lrow * 1024 + k0 + lc16 * 8;
        cp16(sb + AHI_OFF + soff, Ah + goff);
        cp16(sb + AHI_OFF + soff + 64*(SSTRIDE*2), Ah + goff + (size_t)64*1024);
        cp16(sb + ALO_OFF + soff, Al + goff);
        cp16(sb + ALO_OFF + soff + 64*(SSTRIDE*2), Al + goff + (size_t)64*1024);
        cp16(sb + BHI_OFF + soff, Bh + goff);
        cp16(sb + BLO_OFF + soff, Bl + goff);
    };

    float acc[2][4][4];
#pragma unroll
    for (int i = 0; i < 2; i++)
#pragma unroll
        for (int j = 0; j < 4; j++)
#pragma unroll
            for (int t = 0; t < 4; t++) acc[i][j][t] = 0.f;

    load_stage(0, 0);
    cp_commit();

    const int NCH = 1024 / BK;
    for (int ch = 0; ch < NCH; ch++) {
        if (ch + 1 < NCH) { load_stage(ch + 1, (ch + 1) & 1); cp_commit(); }
        if (ch + 1 < NCH) asm volatile("cp.async.wait_group 1;");
        else              asm volatile("cp.async.wait_group 0;");
        __syncthreads();

        const uint32_t sb = sbase + (ch & 1) * STAGE_B;
#pragma unroll
        for (int ks = 0; ks < 2; ks++) {
            const int k16 = ks * 16;
            uint32_t ahi[2][4], alo[2][4];
#pragma unroll
            for (int mf = 0; mf < 2; mf++) {
                const int row = wm * 32 + mf * 16 + (lane & 15);
                const int kc  = k16 + ((lane >> 4) << 3);
                const uint32_t off = (uint32_t)(row * (SSTRIDE*2) + kc * 2);
                ldmatrix4(ahi[mf][0], ahi[mf][1], ahi[mf][2], ahi[mf][3],
                          sb + AHI_OFF + off);
                ldmatrix4(alo[mf][0], alo[mf][1], alo[mf][2], alo[mf][3],
                          sb + ALO_OFF + off);
            }
            uint32_t bhi[4][2], blo[4][2];
#pragma unroll
            for (int nf16 = 0; nf16 < 2; nf16++) {
                const int nrow = wn * 32 + nf16 * 16 + ((lane >> 4) << 3) + (lane & 7);
                const int kc   = k16 + (((lane >> 3) & 1) << 3);
                const uint32_t off = (uint32_t)(nrow * (SSTRIDE*2) + kc * 2);
                ldmatrix4(bhi[nf16*2][0], bhi[nf16*2][1],
                          bhi[nf16*2+1][0], bhi[nf16*2+1][1], sb + BHI_OFF + off);
                ldmatrix4(blo[nf16*2][0], blo[nf16*2][1],
                          blo[nf16*2+1][0], blo[nf16*2+1][1], sb + BLO_OFF + off);
            }
#pragma unroll
            for (int mf = 0; mf < 2; mf++)
#pragma unroll
                for (int nf = 0; nf < 4; nf++) {
                    mma_bf16(acc[mf][nf], ahi[mf], bhi[nf]);
                    mma_bf16(acc[mf][nf], ahi[mf], blo[nf]);
                    mma_bf16(acc[mf][nf], alo[mf], bhi[nf]);
                }
        }
        __syncthreads();
    }

    // ---- epilogue ----
#pragma unroll
    for (int mf = 0; mf < 2; mf++) {
#pragma unroll
        for (int nf = 0; nf < 4; nf++) {
            const int m_base = m0 + wm * 32 + mf * 16;
            const int n = n0 + wn * 32 + nf * 8 + (lane & 3) * 2;
            const int r0 = m_base + (lane >> 2);
            const int r1 = r0 + 8;
            const float v0 = acc[mf][nf][0] * scale;
            const float v1 = acc[mf][nf][1] * scale;
            const float v2 = acc[mf][nf][2] * scale;
            const float v3 = acc[mf][nf][3] * scale;
            if (mode == 0) {
                *(float2*)(Cf + (size_t)r0 * 1024 + n) = make_float2(v0, v1);
                *(float2*)(Cf + (size_t)r1 * 1024 + n) = make_float2(v2, v3);
            } else if (mode == 1) {
                const int h = n >> 6, d = n & 63;
                const int bh0 = ((r0 >> 11) * HEADS) + h;
                const int bh1 = ((r1 >> 11) * HEADS) + h;
                store_hl(Chi, Clo, ((size_t)bh0 * SEQ + (r0 & 2047)) * DK + d, v0, v1);
                store_hl(Chi, Clo, ((size_t)bh1 * SEQ + (r1 & 2047)) * DK + d, v2, v3);
            } else {
                const int h = n >> 6, d = n & 63;
                const int bh0 = ((r0 >> 11) * HEADS) + h;
                const int bh1 = ((r1 >> 11) * HEADS) + h;
                const int s0 = r0 & 2047, s1 = r1 & 2047;
                // transposed [bh][d][s], scalar bf16 stores
                {
                    size_t e = ((size_t)bh0 * DK + d) * SEQ + s0;
                    __nv_bfloat16 h0 = __float2bfloat16(v0);
                    Chi[e] = h0; Clo[e] = __float2bfloat16(v0 - __bfloat162float(h0));
                    e += SEQ;  // d+1
                    __nv_bfloat16 h1 = __float2bfloat16(v1);
                    Chi[e] = h1; Clo[e] = __float2bfloat16(v1 - __bfloat162float(h1));
                }
                {
                    size_t e = ((size_t)bh1 * DK + d) * SEQ + s1;
                    __nv_bfloat16 h2 = __float2bfloat16(v2);
                    Chi[e] = h2; Clo[e] = __float2bfloat16(v2 - __bfloat162float(h2));
                    e += SEQ;
                    __nv_bfloat16 h3 = __float2bfloat16(v3);
                    Chi[e] = h3; Clo[e] = __float2bfloat16(v3 - __bfloat162float(h3));
                }
            }
        }
    }
}

// ---------------- mma.sync flash attention (causal, split-bf16) -------------
// CTA: 128 q-rows x one bh. 8 warps, warp = 16 q-rows x full 64-k width.
// KV blocks of 64 via 2-stage cp.async pipeline. Q pre-scaled by 1/8.
#define ASTR 144                      // smem row stride bytes (72 b16)
#define AQHI 0
#define AQLO 18432
#define ASTG0 36864                   // stage base
#define AKHI 0
#define AKLO 9216
#define AVHI 18432
#define AVLO 27648
#define ASTAGE_B 36864
#define ATT_SMEM (36864 + 2*36864)    // 110592

__global__ __launch_bounds__(256)
void attn_mma_kernel(const __nv_bfloat16* __restrict__ Qhi,
                     const __nv_bfloat16* __restrict__ Qlo,
                     const __nv_bfloat16* __restrict__ Khi,
                     const __nv_bfloat16* __restrict__ Klo,
                     const __nv_bfloat16* __restrict__ Vhi,
                     const __nv_bfloat16* __restrict__ Vlo,
                     __nv_bfloat16* __restrict__ Ohi,
                     __nv_bfloat16* __restrict__ Olo)
{
    extern __shared__ char smem[];
    const uint32_t sbase = smem_u32(smem);
    const int tid = threadIdx.x;
    const int w = tid >> 5;
    const int lane = tid & 31;
    const int qt = blockIdx.x;        // 0..15 (128-row q tiles)
    const int bh = blockIdx.y;        // 0..63

    const __nv_bfloat16* Qh = Qhi + (size_t)bh * SEQ * DK + (size_t)qt * 128 * DK;
    const __nv_bfloat16* Ql = Qlo + (size_t)bh * SEQ * DK + (size_t)qt * 128 * DK;
    const __nv_bfloat16* Kh = Khi + (size_t)bh * SEQ * DK;
    const __nv_bfloat16* Kl = Klo + (size_t)bh * SEQ * DK;
    const __nv_bfloat16* Vh = Vhi + (size_t)bh * DK * SEQ;
    const __nv_bfloat16* Vl = Vlo + (size_t)bh * DK * SEQ;

    // ---- load Q tile (128 x 64 b16, hi+lo) ----
    {
#pragma unroll
        for (int i = 0; i < 4; i++) {
            const int idx = tid + i * 256;       // 0..1023
            const int row = idx >> 3, c = idx & 7;
            const uint32_t so = (uint32_t)(row * ASTR + c * 16);
            const size_t go = (size_t)row * DK + c * 8;
            cp16(sbase + AQHI + so, Qh + go);
            cp16(sbase + AQLO + so, Ql + go);
        }
        cp_commit();
    }

    const int jmax = 2 * qt + 1;
    auto load_kv = [&](int j, int st) {
        const uint32_t sb = sbase + ASTG0 + st * ASTAGE_B;
#pragma unroll
        for (int i = 0; i < 2; i++) {
            const int idx = tid + i * 256;       // 0..511
            const int row = idx >> 3, c = idx & 7;
            const uint32_t so = (uint32_t)(row * ASTR + c * 16);
            const size_t gk = (size_t)(j * 64 + row) * DK + c * 8;
            const size_t gv = (size_t)row * SEQ + j * 64 + c * 8;
            cp16(sb + AKHI + so, Kh + gk);
            cp16(sb + AKLO + so, Kl + gk);
            cp16(sb + AVHI + so, Vh + gv);
            cp16(sb + AVLO + so, Vl + gv);
        }
        cp_commit();
    };

    load_kv(0, 0);

    // wait for Q, load Q fragments (stays in regs)
    asm volatile("cp.async.wait_group 1;");
    __syncthreads();
    uint32_t qhf[4][4], qlf[4][4];
#pragma unroll
    for (int kb = 0; kb < 4; kb++) {
        const int row = w * 16 + (lane & 15);
        const int kc = kb * 16 + ((lane >> 4) << 3);
        const uint32_t off = (uint32_t)(row * ASTR + kc * 2);
        ldmatrix4(qhf[kb][0], qhf[kb][1], qhf[kb][2], qhf[kb][3], sbase + AQHI + off);
        ldmatrix4(qlf[kb][0], qlf[kb][1], qlf[kb][2], qlf[kb][3], sbase + AQLO + off);
    }

    float o[8][4];
#pragma unroll
    for (int nf = 0; nf < 8; nf++)
#pragma unroll
        for (int t = 0; t < 4; t++) o[nf][t] = 0.f;
    float mA = -1e30f, mB = -1e30f, lA = 0.f, lB = 0.f;

    const int rowA_g = qt * 128 + w * 16 + (lane >> 2);
    const int rowB_g = rowA_g + 8;

    for (int j = 0; j <= jmax; j++) {
        if (j < jmax) load_kv(j + 1, (j + 1) & 1);
        if (j < jmax) asm volatile("cp.async.wait_group 1;");
        else          asm volatile("cp.async.wait_group 0;");
        __syncthreads();

        const uint32_t sb = sbase + ASTG0 + (j & 1) * ASTAGE_B;

        // ---- S = Q K^T (3-term split) ----
        float s[8][4];
#pragma unroll
        for (int nf = 0; nf < 8; nf++)
#pragma unroll
            for (int t = 0; t < 4; t++) s[nf][t] = 0.f;
#pragma unroll
        for (int kb = 0; kb < 4; kb++) {
            uint32_t kh[8][2], kl[8][2];
            const uint32_t kcoff = (uint32_t)((kb * 16 + (((lane >> 3) & 1) << 3)) * 2);
            const int nr = ((lane >> 4) << 3) + (lane & 7);
#pragma unroll
            for (int ng = 0; ng < 4; ng++) {
                const uint32_t off = (uint32_t)((ng * 16 + nr) * ASTR) + kcoff;
                ldmatrix4(kh[2*ng][0], kh[2*ng][1], kh[2*ng+1][0], kh[2*ng+1][1],
                          sb + AKHI + off);
                ldmatrix4(kl[2*ng][0], kl[2*ng][1], kl[2*ng+1][0], kl[2*ng+1][1],
                          sb + AKLO + off);
            }
#pragma unroll
            for (int nf = 0; nf < 8; nf++) {
                mma_bf16(s[nf], qhf[kb], kh[nf]);
                mma_bf16(s[nf], qhf[kb], kl[nf]);
                mma_bf16(s[nf], qlf[kb], kh[nf]);
            }
        }

        // ---- causal mask (only near diagonal) ----
        if (j >= 2 * qt) {
#pragma unroll
            for (int nf = 0; nf < 8; nf++) {
                const int c0 = j * 64 + nf * 8 + (lane & 3) * 2;
                if (c0 > rowA_g)     s[nf][0] = -1e30f;
                if (c0 + 1 > rowA_g) s[nf][1] = -1e30f;
                if (c0 > rowB_g)     s[nf][2] = -1e30f;
                if (c0 + 1 > rowB_g) s[nf][3] = -1e30f;
            }
        }

        // ---- streaming softmax (rows in registers, quad shfl) ----
        float bmA = -1e30f, bmB = -1e30f;
#pragma unroll
        for (int nf = 0; nf < 8; nf++) {
            bmA = fmaxf(bmA, fmaxf(s[nf][0], s[nf][1]));
            bmB = fmaxf(bmB, fmaxf(s[nf][2], s[nf][3]));
        }
        bmA = fmaxf(bmA, __shfl_xor_sync(0xffffffffu, bmA, 1));
        bmA = fmaxf(bmA, __shfl_xor_sync(0xffffffffu, bmA, 2));
        bmB = fmaxf(bmB, __shfl_xor_sync(0xffffffffu, bmB, 1));
        bmB = fmaxf(bmB, __shfl_xor_sync(0xffffffffu, bmB, 2));
        const float mnA = fmaxf(mA, bmA);
        const float mnB = fmaxf(mB, bmB);
        const float alA = __expf(mA - mnA);
        const float alB = __expf(mB - mnB);
        mA = mnA; mB = mnB;

        float sumA = 0.f, sumB = 0.f;
#pragma unroll
        for (int nf = 0; nf < 8; nf++) {
            s[nf][0] = __expf(s[nf][0] - mnA);
            s[nf][1] = __expf(s[nf][1] - mnA);
            s[nf][2] = __expf(s[nf][2] - mnB);
            s[nf][3] = __expf(s[nf][3] - mnB);
            sumA += s[nf][0] + s[nf][1];
            sumB += s[nf][2] + s[nf][3];
        }
        sumA += __shfl_xor_sync(0xffffffffu, sumA, 1);
        sumA += __shfl_xor_sync(0xffffffffu, sumA, 2);
        sumB += __shfl_xor_sync(0xffffffffu, sumB, 1);
        sumB += __shfl_xor_sync(0xffffffffu, sumB, 2);
        lA = lA * alA + sumA;
        lB = lB * alB + sumB;

        // ---- rescale O ----
#pragma unroll
        for (int nf = 0; nf < 8; nf++) {
            o[nf][0] *= alA; o[nf][1] *= alA;
            o[nf][2] *= alB; o[nf][3] *= alB;
        }

        // ---- P frags: split hi/lo, direct acc->A-frag mapping ----
        uint32_t pf_hi[4][4], pf_lo[4][4];
#pragma unroll
        for (int t = 0; t < 4; t++) {
            float r0, r1;
            pf_hi[t][0] = pack_hi(s[2*t][0],   s[2*t][1],   r0, r1); pf_lo[t][0] = pack_bf(r0, r1);
            pf_hi[t][1] = pack_hi(s[2*t][2],   s[2*t][3],   r0, r1); pf_lo[t][1] = pack_bf(r0, r1);
            pf_hi[t][2] = pack_hi(s[2*t+1][0], s[2*t+1][1], r0, r1); pf_lo[t][2] = pack_bf(r0, r1);
            pf_hi[t][3] = pack_hi(s[2*t+1][2], s[2*t+1][3], r0, r1); pf_lo[t][3] = pack_bf(r0, r1);
        }

        // ---- O += P V (3-term split), V^T smem [d][kpos] ----
#pragma unroll
        for (int t = 0; t < 4; t++) {
            uint32_t vh[8][2], vl[8][2];
            const uint32_t kcoff = (uint32_t)((t * 16 + (((lane >> 3) & 1) << 3)) * 2);
            const int nr = ((lane >> 4) << 3) + (lane & 7);
#pragma unroll
            for (int ng = 0; ng < 4; ng++) {
                const uint32_t off = (uint32_t)((ng * 16 + nr) * ASTR) + kcoff;
                ldmatrix4(vh[2*ng][0], vh[2*ng][1], vh[2*ng+1][0], vh[2*ng+1][1],
                          sb + AVHI + off);
                ldmatrix4(vl[2*ng][0], vl[2*ng][1], vl[2*ng+1][0], vl[2*ng+1][1],
                          sb + AVLO + off);
            }
#pragma unroll
            for (int nf = 0; nf < 8; nf++) {
                mma_bf16(o[nf], pf_hi[t], vh[nf]);
                mma_bf16(o[nf], pf_hi[t], vl[nf]);
                mma_bf16(o[nf], pf_lo[t], vh[nf]);
            }
        }
        __syncthreads();
    }

    // ---- normalize & write bf16 hi/lo to [b, s, h*64+d] ----
    const float invA = 1.f / lA;
    const float invB = 1.f / lB;
    const int b = bh >> 4, h = bh & 15;
    const size_t mAi = (size_t)(b * SEQ) + (size_t)(rowA_g & 2047);
    const size_t mBi = mAi + 8;
#pragma unroll
    for (int nf = 0; nf < 8; nf++) {
        const int col = h * 64 + nf * 8 + (lane & 3) * 2;
        store_hl(Ohi, Olo, mAi * D_MODEL + col, o[nf][0] * invA, o[nf][1] * invA);
        store_hl(Ohi, Olo, mBi * D_MODEL + col, o[nf][2] * invB, o[nf][3] * invB);
    }
}

// ---------------------------------------------------------------------------
extern "C" void kernel_launch(void* const* d_in, const int* in_sizes, int n_in,
                              void* d_out, int out_size)
{
    (void)in_sizes; (void)n_in; (void)out_size;
    const float* x  = (const float*)d_in[0];
    const float* Wq = (const float*)d_in[1];
    const float* Wk = (const float*)d_in[2];
    const float* Wv = (const float*)d_in[3];
    const float* Wo = (const float*)d_in[4];
    float* out = (float*)d_out;

    __nv_bfloat16 *xhi, *xlo, *whi, *wlo;
    __nv_bfloat16 *qhi, *qlo, *khi, *klo, *vhi, *vlo, *ahi, *alo;
    cudaGetSymbolAddress((void**)&xhi, g_xhi);
    cudaGetSymbolAddress((void**)&xlo, g_xlo);
    cudaGetSymbolAddress((void**)&whi, g_whi);
    cudaGetSymbolAddress((void**)&wlo, g_wlo);
    cudaGetSymbolAddress((void**)&qhi, g_qhi);
    cudaGetSymbolAddress((void**)&qlo, g_qlo);
    cudaGetSymbolAddress((void**)&khi, g_khi);
    cudaGetSymbolAddress((void**)&klo, g_klo);
    cudaGetSymbolAddress((void**)&vhi, g_vhi);
    cudaGetSymbolAddress((void**)&vlo, g_vlo);
    cudaGetSymbolAddress((void**)&ahi, g_ahi);
    cudaGetSymbolAddress((void**)&alo, g_alo);

    cudaFuncSetAttribute(gemm_mma_kernel,
                         cudaFuncAttributeMaxDynamicSharedMemorySize, GEMM_SMEM);
    cudaFuncSetAttribute(attn_mma_kernel,
                         cudaFuncAttributeMaxDynamicSharedMemorySize, ATT_SMEM);

    const int WN4 = D_MODEL * D_MODEL / 4;
    const int XN4 = MTOT * D_MODEL / 4;
    const float* Ws[4] = {Wq, Wk, Wv, Wo};

    split_kernel<<<XN4 / 256, 256>>>(x, xhi, xlo, XN4);
    for (int i = 0; i < 4; i++)
        split_kernel<<<WN4 / 256, 256>>>(Ws[i], whi + (size_t)i * D_MODEL * D_MODEL,
                                         wlo + (size_t)i * D_MODEL * D_MODEL, WN4);

    dim3 gg(D_MODEL / BN, MTOT / BM);      // (16, 64)
    const size_t WSZ = (size_t)D_MODEL * D_MODEL;

    gemm_mma_kernel<<<gg, 256, GEMM_SMEM>>>(xhi, xlo, whi + 0*WSZ, wlo + 0*WSZ,
                                            nullptr, qhi, qlo, 0.125f, 1);
    gemm_mma_kernel<<<gg, 256, GEMM_SMEM>>>(xhi, xlo, whi + 1*WSZ, wlo + 1*WSZ,
                                            nullptr, khi, klo, 1.0f, 1);
    gemm_mma_kernel<<<gg, 256, GEMM_SMEM>>>(xhi, xlo, whi + 2*WSZ, wlo + 2*WSZ,
                                            nullptr, vhi, vlo, 1.0f, 2);

    attn_mma_kernel<<<dim3(SEQ / 128, BH), 256, ATT_SMEM>>>(qhi, qlo, khi, klo,
                                                            vhi, vlo, ahi, alo);

    gemm_mma_kernel<<<gg, 256, GEMM_SMEM>>>(ahi, alo, whi + 3*WSZ, wlo + 3*WSZ,
                                            out, nullptr, nullptr, 1.0f, 0);
}